// round 10
// baseline (speedup 1.0000x reference)
#include <cuda_runtime.h>

// 2-layer LSTM, B=2048 T=2048 H1=36 H2=1, fp32.
// R9 = R7 structure (lag-1 L2, flattened loop, hd4 LDS.128, reg W, no syncwarp)
//   + sigmoid 0.5-fold into weights (exact, from R8)
//   + extra units via R7 register-W scheme (no per-j scalar LDS)
//   + NEW L2: 16 lanes/seq, lane=(s:1)(q:2)(jg:2), 9 MACs/lane,
//     2-level shfl_xor reduce (1,2), 4-gather, xor-16 seq swap.

#define FULLMASK 0xffffffffu
#define H1C 36
#define TT 2048

__device__ __forceinline__ float2 ffma2(float2 a, float2 b, float2 c) {
    float2 d;
    asm("fma.rn.f32x2 %0, %1, %2, %3;"
        : "=l"(reinterpret_cast<unsigned long long&>(d))
        : "l"(reinterpret_cast<unsigned long long&>(a)),
          "l"(reinterpret_cast<unsigned long long&>(b)),
          "l"(reinterpret_cast<unsigned long long&>(c)));
    return d;
}
__device__ __forceinline__ float tanha(float x) {
    float y;
    asm("tanh.approx.f32 %0, %1;" : "=f"(y) : "f"(x));
    return y;
}

struct Smem {
    float4 hd4[40];   // (hA, hA, hB, hB) per unit; [36..39] pad = 0
    float2 hr[40];    // (relu(hA), relu(hB))
};

__global__ void __launch_bounds__(32)
lstm2_kernel(const float* __restrict__ x,
             const float* __restrict__ W_ih1, const float* __restrict__ W_hh1,
             const float* __restrict__ b_ih1, const float* __restrict__ b_hh1,
             const float* __restrict__ W_ih2, const float* __restrict__ W_hh2,
             const float* __restrict__ b_ih2, const float* __restrict__ b_hh2,
             float* __restrict__ out)
{
    __shared__ Smem sm;
    const int lane = threadIdx.x;
    const int seqA = blockIdx.x * 2;

    // ---- main slots: (i,f,g,o) of unit = lane; sigmoid rows pre-scaled 0.5
    const int r0 = lane, r1 = H1C + lane, r2 = 2 * H1C + lane, r3 = 3 * H1C + lane;
    float2 Wp01[H1C], Wp23[H1C];
    #pragma unroll
    for (int j = 0; j < H1C; ++j) {
        Wp01[j] = make_float2(0.5f * W_hh1[r0 * H1C + j], 0.5f * W_hh1[r1 * H1C + j]);
        Wp23[j] = make_float2(W_hh1[r2 * H1C + j], 0.5f * W_hh1[r3 * H1C + j]);
    }
    const float2 wih01 = make_float2(0.5f * W_ih1[r0], 0.5f * W_ih1[r1]);
    const float2 wih23 = make_float2(W_ih1[r2], 0.5f * W_ih1[r3]);
    const float2 bs01  = make_float2(0.5f * (b_ih1[r0] + b_hh1[r0]),
                                     0.5f * (b_ih1[r1] + b_hh1[r1]));
    const float2 bs23  = make_float2(b_ih1[r2] + b_hh1[r2],
                                     0.5f * (b_ih1[r3] + b_hh1[r3]));

    // ---- extra units 32..35 (R7 scheme): lane<16 computes gate (lane>>2)
    //      of unit 32+(lane&3), for both seqs; sigmoid rows pre-scaled 0.5
    const bool eok = lane < 16;
    const int  gE  = lane >> 2;           // gate for extra slot (lane<16)
    const int  u   = lane & 3;            // unit - 32
    const float esO = (gE == 2) ? 1.0f : 0.5f;   // output coeff (valid lane<16)
    const float eoO = (gE == 2) ? 0.0f : 0.5f;
    const int  r4  = eok ? (gE * H1C + 32 + u) : 0;
    const float esW = (gE == 2) ? 1.0f : 0.5f;
    float W4[H1C];
    #pragma unroll
    for (int j = 0; j < H1C; ++j)
        W4[j] = eok ? (esW * W_hh1[r4 * H1C + j]) : 0.0f;
    const float wih4 = eok ? (esW * W_ih1[r4]) : 0.0f;
    const float bs4  = eok ? (esW * (b_ih1[r4] + b_hh1[r4])) : 0.0f;

    // ---- L2: lane = (s:1)(q:2)(jg:2); 9 MACs per lane over j = jg*9 + m
    const int sL2 = lane >> 4;            // seq
    const int q2  = (lane >> 2) & 3;      // gate
    const int jg  = lane & 3;             // j-group
    const float asc = (q2 == 2) ? 1.0f : 0.5f;
    const float aoc = (q2 == 2) ? 0.0f : 0.5f;
    float w2r[9];
    #pragma unroll
    for (int m = 0; m < 9; ++m)
        w2r[m] = asc * W_ih2[q2 * H1C + jg * 9 + m];
    const float b2q = asc * (b_ih2[q2] + b_hh2[q2]);
    const float whq = asc * W_hh2[q2];

    if (lane < 20) {
        sm.hd4[2 * lane]     = make_float4(0.f, 0.f, 0.f, 0.f);
        sm.hd4[2 * lane + 1] = make_float4(0.f, 0.f, 0.f, 0.f);
    }
    sm.hr[lane] = make_float2(0.f, 0.f);
    if (lane < 8) sm.hr[32 + lane] = make_float2(0.f, 0.f);
    __syncthreads();

    const float* xA = x   + (size_t)seqA * TT;
    const float* xB = xA + TT;
    float*       oA = out + (size_t)seqA * TT;
    float*       oB = oA + TT;

    float cA = 0.f, cB = 0.f, cEA = 0.f, cEB = 0.f;
    float l2c = 0.f, l2h = 0.f;           // per-lane: seq sL2's layer-2 state
    float obA = 0.f, obB = 0.f;

    float2 aA01, aA23, aB01, aB23;
    float  aA4, aB4;

    // ---- L1 gate accumulation for step t (reads hd4(t-1))
    auto jloop = [&](float xa, float xb) {
        aA01 = ffma2(make_float2(xa, xa), wih01, bs01);
        aA23 = ffma2(make_float2(xa, xa), wih23, bs23);
        aB01 = ffma2(make_float2(xb, xb), wih01, bs01);
        aB23 = ffma2(make_float2(xb, xb), wih23, bs23);
        aA4  = fmaf(xa, wih4, bs4);
        aB4  = fmaf(xb, wih4, bs4);
        #pragma unroll
        for (int j = 0; j < H1C; ++j) {
            const float4 h4 = sm.hd4[j];
            const float2 hA2 = make_float2(h4.x, h4.y);
            const float2 hB2 = make_float2(h4.z, h4.w);
            aA01 = ffma2(Wp01[j], hA2, aA01);
            aA23 = ffma2(Wp23[j], hA2, aA23);
            aB01 = ffma2(Wp01[j], hB2, aB01);
            aB23 = ffma2(Wp23[j], hB2, aB23);
            aA4  = fmaf(W4[j], h4.x, aA4);
            aB4  = fmaf(W4[j], h4.z, aB4);
        }
    };

    // ---- L2 for the PREVIOUS step (reads hr(t-1)); tpmod = (t-1)&31
    auto l2step = [&](int tpmod) {
        float sS = 0.f;
        #pragma unroll
        for (int m = 0; m < 9; ++m) {
            const float hv = *(reinterpret_cast<const float*>(&sm.hr[jg * 9 + m]) + sL2);
            sS = fmaf(w2r[m], hv, sS);
        }
        sS += __shfl_xor_sync(FULLMASK, sS, 1);
        sS += __shfl_xor_sync(FULLMASK, sS, 2);
        const float v   = fmaf(whq, l2h, sS + b2q);
        const float act = fmaf(asc, tanha(v), aoc);
        const int b16 = lane & 16;
        const float iV = __shfl_sync(FULLMASK, act, b16 + 0);
        const float fV = __shfl_sync(FULLMASK, act, b16 + 4);
        const float gV = __shfl_sync(FULLMASK, act, b16 + 8);
        const float oV = __shfl_sync(FULLMASK, act, b16 + 12);
        l2c = fmaf(fV, l2c, iV * gV);
        l2h = oV * tanha(l2c);
        const float hO = __shfl_xor_sync(FULLMASK, l2h, 16);
        const float hAv = sL2 ? hO : l2h;
        const float hBv = sL2 ? l2h : hO;
        obA = (tpmod == lane) ? hAv : obA;
        obB = (tpmod == lane) ? hBv : obB;
    };

    // ---- activations for step t (writes hd4(t), hr(t))
    auto acts = [&]() {
        {
            const float iA = fmaf(0.5f, tanha(aA01.x), 0.5f);
            const float fA = fmaf(0.5f, tanha(aA01.y), 0.5f);
            const float gA = tanha(aA23.x);
            const float oAa = fmaf(0.5f, tanha(aA23.y), 0.5f);
            cA = fmaf(fA, cA, iA * gA);
            const float hA = oAa * tanha(cA);
            const float iB = fmaf(0.5f, tanha(aB01.x), 0.5f);
            const float fB = fmaf(0.5f, tanha(aB01.y), 0.5f);
            const float gB = tanha(aB23.x);
            const float oBa = fmaf(0.5f, tanha(aB23.y), 0.5f);
            cB = fmaf(fB, cB, iB * gB);
            const float hB = oBa * tanha(cB);
            sm.hd4[lane] = make_float4(hA, hA, hB, hB);
            sm.hr[lane]  = make_float2(fmaxf(hA, 0.f), fmaxf(hB, 0.f));
        }
        {   // extra units 32..35 (pre-gather acts; weights pre-scaled)
            const float eAv = fmaf(esO, tanha(aA4), eoO);
            const float eBv = fmaf(esO, tanha(aB4), eoO);
            const float iA = __shfl_sync(FULLMASK, eAv, u);
            const float fA = __shfl_sync(FULLMASK, eAv, u + 4);
            const float gA = __shfl_sync(FULLMASK, eAv, u + 8);
            const float oAe = __shfl_sync(FULLMASK, eAv, u + 12);
            const float iB = __shfl_sync(FULLMASK, eBv, u);
            const float fB = __shfl_sync(FULLMASK, eBv, u + 4);
            const float gB = __shfl_sync(FULLMASK, eBv, u + 8);
            const float oBe = __shfl_sync(FULLMASK, eBv, u + 12);
            cEA = fmaf(fA, cEA, iA * gA);
            cEB = fmaf(fB, cEB, iB * gB);
            const float hEA = oAe * tanha(cEA);
            const float hEB = oBe * tanha(cEB);
            if (lane < 4) {
                sm.hd4[32 + u] = make_float4(hEA, hEA, hEB, hEB);
                sm.hr[32 + u]  = make_float2(fmaxf(hEA, 0.f), fmaxf(hEB, 0.f));
            }
        }
    };

    float xcA = xA[lane];          // x chunk 0
    float xcB = xB[lane];

    // ---- peel step 0 (h = 0: preacts are x/bias-only)
    {
        const float xa = __shfl_sync(FULLMASK, xcA, 0);
        const float xb = __shfl_sync(FULLMASK, xcB, 0);
        aA01 = ffma2(make_float2(xa, xa), wih01, bs01);
        aA23 = ffma2(make_float2(xa, xa), wih23, bs23);
        aB01 = ffma2(make_float2(xb, xb), wih01, bs01);
        aB23 = ffma2(make_float2(xb, xb), wih23, bs23);
        aA4  = fmaf(xa, wih4, bs4);
        aB4  = fmaf(xb, wih4, bs4);
        acts();
    }

    // ---- main: blocks 0..62 (inner st=1..31, then first step of next chunk)
    for (int tb = 0; tb < 63; ++tb) {
        const float xnA = xA[(tb + 1) * 32 + lane];
        const float xnB = xB[(tb + 1) * 32 + lane];

        #pragma unroll 1
        for (int st = 1; st < 32; ++st) {
            const float xa = __shfl_sync(FULLMASK, xcA, st);
            const float xb = __shfl_sync(FULLMASK, xcB, st);
            jloop(xa, xb);
            l2step(st - 1);
            acts();
        }
        {   // first step of next chunk; its L2 closes this chunk
            const float xa = __shfl_sync(FULLMASK, xnA, 0);
            const float xb = __shfl_sync(FULLMASK, xnB, 0);
            jloop(xa, xb);
            l2step(31);
            acts();
        }
        oA[tb * 32 + lane] = obA;
        oB[tb * 32 + lane] = obB;
        xcA = xnA;
        xcB = xnB;
    }

    // ---- last block (tb = 63)
    #pragma unroll 1
    for (int st = 1; st < 32; ++st) {
        const float xa = __shfl_sync(FULLMASK, xcA, st);
        const float xb = __shfl_sync(FULLMASK, xcB, st);
        jloop(xa, xb);
        l2step(st - 1);
        acts();
    }
    l2step(31);
    oA[63 * 32 + lane] = obA;
    oB[63 * 32 + lane] = obB;
}

extern "C" void kernel_launch(void* const* d_in, const int* in_sizes, int n_in,
                              void* d_out, int out_size)
{
    const float* x     = (const float*)d_in[0];
    const float* W_ih1 = (const float*)d_in[1];
    const float* W_hh1 = (const float*)d_in[2];
    const float* b_ih1 = (const float*)d_in[3];
    const float* b_hh1 = (const float*)d_in[4];
    const float* W_ih2 = (const float*)d_in[5];
    const float* W_hh2 = (const float*)d_in[6];
    const float* b_ih2 = (const float*)d_in[7];
    const float* b_hh2 = (const float*)d_in[8];

    const int B = in_sizes[0] / TT;   // x is [B, T, 1]
    lstm2_kernel<<<B / 2, 32>>>(x, W_ih1, W_hh1, b_ih1, b_hh1,
                                W_ih2, W_hh2, b_ih2, b_hh2,
                                (float*)d_out);
}

// round 12
// speedup vs baseline: 1.0531x; 1.0531x over previous
#include <cuda_runtime.h>

// 2-layer LSTM, B=2048 T=2048 H1=36 H2=1, fp32.
// R11 = R7 dataflow (single hr, lag-1 L2, hd4 LDS.128, reg W) +
//   - body order {l2step(t-1); jloop(t); acts(t)}  (L2 chain ahead of
//     independent FMA stream for in-order stall filling)
//   - __syncwarp() after acts: explicit same-warp STS->LDS ordering point
//     (B300 STS has no store-forward; scoreboard does not cover SMEM RAW)
//   - sigmoid 0.5-fold into weights (exact, from R8)

#define FULLMASK 0xffffffffu
#define H1C 36
#define TT 2048

__device__ __forceinline__ float2 ffma2(float2 a, float2 b, float2 c) {
    float2 d;
    asm("fma.rn.f32x2 %0, %1, %2, %3;"
        : "=l"(reinterpret_cast<unsigned long long&>(d))
        : "l"(reinterpret_cast<unsigned long long&>(a)),
          "l"(reinterpret_cast<unsigned long long&>(b)),
          "l"(reinterpret_cast<unsigned long long&>(c)));
    return d;
}
__device__ __forceinline__ float tanha(float x) {
    float y;
    asm("tanh.approx.f32 %0, %1;" : "=f"(y) : "f"(x));
    return y;
}

struct Smem {
    float4 hd4[40];   // (hA, hA, hB, hB) per unit; [36..39] pad = 0
    float2 hr[40];    // (relu(hA), relu(hB)); [36..39] pad = 0
};

__global__ void __launch_bounds__(32)
lstm2_kernel(const float* __restrict__ x,
             const float* __restrict__ W_ih1, const float* __restrict__ W_hh1,
             const float* __restrict__ b_ih1, const float* __restrict__ b_hh1,
             const float* __restrict__ W_ih2, const float* __restrict__ W_hh2,
             const float* __restrict__ b_ih2, const float* __restrict__ b_hh2,
             float* __restrict__ out)
{
    __shared__ Smem sm;
    const int lane = threadIdx.x;
    const int seqA = blockIdx.x * 2;

    // ---- main slots: (i,f,g,o) of unit = lane; sigmoid rows pre-scaled 0.5
    const int r0 = lane, r1 = H1C + lane, r2 = 2 * H1C + lane, r3 = 3 * H1C + lane;
    float2 Wp01[H1C], Wp23[H1C];
    #pragma unroll
    for (int j = 0; j < H1C; ++j) {
        Wp01[j] = make_float2(0.5f * W_hh1[r0 * H1C + j], 0.5f * W_hh1[r1 * H1C + j]);
        Wp23[j] = make_float2(W_hh1[r2 * H1C + j], 0.5f * W_hh1[r3 * H1C + j]);
    }
    const float2 wih01 = make_float2(0.5f * W_ih1[r0], 0.5f * W_ih1[r1]);
    const float2 wih23 = make_float2(W_ih1[r2], 0.5f * W_ih1[r3]);
    const float2 bs01  = make_float2(0.5f * (b_ih1[r0] + b_hh1[r0]),
                                     0.5f * (b_ih1[r1] + b_hh1[r1]));
    const float2 bs23  = make_float2(b_ih1[r2] + b_hh1[r2],
                                     0.5f * (b_ih1[r3] + b_hh1[r3]));

    // ---- extra units 32..35: lane<16 -> gate (lane>>2) of unit 32+(lane&3)
    const bool eok = lane < 16;
    const int  gE  = lane >> 2;
    const int  u   = lane & 3;
    const float esO = (gE == 2) ? 1.0f : 0.5f;
    const float eoO = (gE == 2) ? 0.0f : 0.5f;
    const int  r4  = eok ? (gE * H1C + 32 + u) : 0;
    const float esW = (gE == 2) ? 1.0f : 0.5f;
    float W4[H1C];
    #pragma unroll
    for (int j = 0; j < H1C; ++j)
        W4[j] = eok ? (esW * W_hh1[r4 * H1C + j]) : 0.0f;
    const float wih4 = eok ? (esW * W_ih1[r4]) : 0.0f;
    const float bs4  = eok ? (esW * (b_ih1[r4] + b_hh1[r4])) : 0.0f;

    // ---- L2: lane handles gate q over j = j0 + 8m; asc folded into weights
    const int q  = lane & 3;
    const int j0 = lane >> 2;
    const float asc = (q == 2) ? 1.0f : 0.5f;
    const float aoc = (q == 2) ? 0.0f : 0.5f;
    float w2r[4];
    #pragma unroll
    for (int m = 0; m < 4; ++m)
        w2r[m] = asc * W_ih2[q * H1C + j0 + 8 * m];
    const float w2x = (j0 < 4) ? asc * W_ih2[q * H1C + 32 + j0] : 0.0f;
    const float b2q = asc * (b_ih2[q] + b_hh2[q]);
    const float whq = asc * W_hh2[q];

    if (lane < 20) {
        sm.hd4[2 * lane]     = make_float4(0.f, 0.f, 0.f, 0.f);
        sm.hd4[2 * lane + 1] = make_float4(0.f, 0.f, 0.f, 0.f);
    }
    sm.hr[lane] = make_float2(0.f, 0.f);
    if (lane < 8) sm.hr[32 + lane] = make_float2(0.f, 0.f);
    __syncthreads();

    const float* xA = x   + (size_t)seqA * TT;
    const float* xB = xA + TT;
    float*       oA = out + (size_t)seqA * TT;
    float*       oB = oA + TT;

    float cA = 0.f, cB = 0.f, cEA = 0.f, cEB = 0.f;
    float l2cA = 0.f, l2cB = 0.f, l2hA = 0.f, l2hB = 0.f;
    float obA = 0.f, obB = 0.f;

    float2 aA01, aA23, aB01, aB23;
    float  aA4, aB4;

    // ---- L1 gate accumulation for step t (reads hd4(t-1))
    auto jloop = [&](float xa, float xb) {
        aA01 = ffma2(make_float2(xa, xa), wih01, bs01);
        aA23 = ffma2(make_float2(xa, xa), wih23, bs23);
        aB01 = ffma2(make_float2(xb, xb), wih01, bs01);
        aB23 = ffma2(make_float2(xb, xb), wih23, bs23);
        aA4  = fmaf(xa, wih4, bs4);
        aB4  = fmaf(xb, wih4, bs4);
        #pragma unroll
        for (int j = 0; j < H1C; ++j) {
            const float4 h4 = sm.hd4[j];
            const float2 hA2 = make_float2(h4.x, h4.y);
            const float2 hB2 = make_float2(h4.z, h4.w);
            aA01 = ffma2(Wp01[j], hA2, aA01);
            aA23 = ffma2(Wp23[j], hA2, aA23);
            aB01 = ffma2(Wp01[j], hB2, aB01);
            aB23 = ffma2(Wp23[j], hB2, aB23);
            aA4  = fmaf(W4[j], h4.x, aA4);
            aB4  = fmaf(W4[j], h4.z, aB4);
        }
    };

    // ---- L2 for the PREVIOUS step (reads hr(t-1)); tpmod = (t-1)&31
    auto l2step = [&](int tpmod) {
        float sA = 0.f, sB = 0.f;
        #pragma unroll
        for (int m = 0; m < 4; ++m) {
            const float2 hh = sm.hr[j0 + 8 * m];
            sA = fmaf(w2r[m], hh.x, sA);
            sB = fmaf(w2r[m], hh.y, sB);
        }
        const float2 hx = sm.hr[32 + j0];
        sA = fmaf(w2x, hx.x, sA);
        sB = fmaf(w2x, hx.y, sB);
        #pragma unroll
        for (int off = 4; off <= 16; off <<= 1) {
            sA += __shfl_xor_sync(FULLMASK, sA, off);
            sB += __shfl_xor_sync(FULLMASK, sB, off);
        }
        const float vA = fmaf(whq, l2hA, sA + b2q);
        const float vB = fmaf(whq, l2hB, sB + b2q);
        const float aAct = fmaf(asc, tanha(vA), aoc);
        const float bAct = fmaf(asc, tanha(vB), aoc);
        const int base = lane & ~3;
        const float iA = __shfl_sync(FULLMASK, aAct, base + 0);
        const float fA = __shfl_sync(FULLMASK, aAct, base + 1);
        const float gA = __shfl_sync(FULLMASK, aAct, base + 2);
        const float oA2 = __shfl_sync(FULLMASK, aAct, base + 3);
        const float iB = __shfl_sync(FULLMASK, bAct, base + 0);
        const float fB = __shfl_sync(FULLMASK, bAct, base + 1);
        const float gB = __shfl_sync(FULLMASK, bAct, base + 2);
        const float oB2 = __shfl_sync(FULLMASK, bAct, base + 3);
        l2cA = fmaf(fA, l2cA, iA * gA);
        l2hA = oA2 * tanha(l2cA);
        l2cB = fmaf(fB, l2cB, iB * gB);
        l2hB = oB2 * tanha(l2cB);
        obA = (tpmod == lane) ? l2hA : obA;
        obB = (tpmod == lane) ? l2hB : obB;
    };

    // ---- activations for step t (writes hd4(t), hr(t)); ends with syncwarp
    auto acts = [&]() {
        {
            const float iA = fmaf(0.5f, tanha(aA01.x), 0.5f);
            const float fA = fmaf(0.5f, tanha(aA01.y), 0.5f);
            const float gA = tanha(aA23.x);
            const float oAa = fmaf(0.5f, tanha(aA23.y), 0.5f);
            cA = fmaf(fA, cA, iA * gA);
            const float hA = oAa * tanha(cA);
            const float iB = fmaf(0.5f, tanha(aB01.x), 0.5f);
            const float fB = fmaf(0.5f, tanha(aB01.y), 0.5f);
            const float gB = tanha(aB23.x);
            const float oBa = fmaf(0.5f, tanha(aB23.y), 0.5f);
            cB = fmaf(fB, cB, iB * gB);
            const float hB = oBa * tanha(cB);
            sm.hd4[lane] = make_float4(hA, hA, hB, hB);
            sm.hr[lane]  = make_float2(fmaxf(hA, 0.f), fmaxf(hB, 0.f));
        }
        {   // extra units 32..35
            const float eAv = fmaf(esO, tanha(aA4), eoO);
            const float eBv = fmaf(esO, tanha(aB4), eoO);
            const float iA = __shfl_sync(FULLMASK, eAv, u);
            const float fA = __shfl_sync(FULLMASK, eAv, u + 4);
            const float gA = __shfl_sync(FULLMASK, eAv, u + 8);
            const float oAe = __shfl_sync(FULLMASK, eAv, u + 12);
            const float iB = __shfl_sync(FULLMASK, eBv, u);
            const float fB = __shfl_sync(FULLMASK, eBv, u + 4);
            const float gB = __shfl_sync(FULLMASK, eBv, u + 8);
            const float oBe = __shfl_sync(FULLMASK, eBv, u + 12);
            cEA = fmaf(fA, cEA, iA * gA);
            cEB = fmaf(fB, cEB, iB * gB);
            const float hEA = oAe * tanha(cEA);
            const float hEB = oBe * tanha(cEB);
            if (lane < 4) {
                sm.hd4[32 + u] = make_float4(hEA, hEA, hEB, hEB);
                sm.hr[32 + u]  = make_float2(fmaxf(hEA, 0.f), fmaxf(hEB, 0.f));
            }
        }
        __syncwarp();   // order this step's STS before any later body's LDS
    };

    float xcA = xA[lane];          // x chunk 0
    float xcB = xB[lane];

    // ---- peel step 0 (h = 0: preacts are x/bias-only)
    {
        const float xa = __shfl_sync(FULLMASK, xcA, 0);
        const float xb = __shfl_sync(FULLMASK, xcB, 0);
        aA01 = ffma2(make_float2(xa, xa), wih01, bs01);
        aA23 = ffma2(make_float2(xa, xa), wih23, bs23);
        aB01 = ffma2(make_float2(xb, xb), wih01, bs01);
        aB23 = ffma2(make_float2(xb, xb), wih23, bs23);
        aA4  = fmaf(xa, wih4, bs4);
        aB4  = fmaf(xb, wih4, bs4);
        acts();
    }

    // ---- main: blocks 0..62 (inner st=1..31, then first step of next chunk)
    for (int tb = 0; tb < 63; ++tb) {
        const float xnA = xA[(tb + 1) * 32 + lane];
        const float xnB = xB[(tb + 1) * 32 + lane];

        #pragma unroll 1
        for (int st = 1; st < 32; ++st) {
            const float xa = __shfl_sync(FULLMASK, xcA, st);
            const float xb = __shfl_sync(FULLMASK, xcB, st);
            l2step(st - 1);      // L2(t-1) first: chain overlaps jloop's FMAs
            jloop(xa, xb);
            acts();
        }
        {   // first step of next chunk; its L2 closes this chunk
            const float xa = __shfl_sync(FULLMASK, xnA, 0);
            const float xb = __shfl_sync(FULLMASK, xnB, 0);
            l2step(31);
            jloop(xa, xb);
            acts();
        }
        oA[tb * 32 + lane] = obA;
        oB[tb * 32 + lane] = obB;
        xcA = xnA;
        xcB = xnB;
    }

    // ---- last block (tb = 63)
    #pragma unroll 1
    for (int st = 1; st < 32; ++st) {
        const float xa = __shfl_sync(FULLMASK, xcA, st);
        const float xb = __shfl_sync(FULLMASK, xcB, st);
        l2step(st - 1);
        jloop(xa, xb);
        acts();
    }
    l2step(31);
    oA[63 * 32 + lane] = obA;
    oB[63 * 32 + lane] = obB;
}

extern "C" void kernel_launch(void* const* d_in, const int* in_sizes, int n_in,
                              void* d_out, int out_size)
{
    const float* x     = (const float*)d_in[0];
    const float* W_ih1 = (const float*)d_in[1];
    const float* W_hh1 = (const float*)d_in[2];
    const float* b_ih1 = (const float*)d_in[3];
    const float* b_hh1 = (const float*)d_in[4];
    const float* W_ih2 = (const float*)d_in[5];
    const float* W_hh2 = (const float*)d_in[6];
    const float* b_ih2 = (const float*)d_in[7];
    const float* b_hh2 = (const float*)d_in[8];

    const int B = in_sizes[0] / TT;   // x is [B, T, 1]
    lstm2_kernel<<<B / 2, 32>>>(x, W_ih1, W_hh1, b_ih1, b_hh1,
                                W_ih2, W_hh2, b_ih2, b_hh2,
                                (float*)d_out);
}